// round 10
// baseline (speedup 1.0000x reference)
#include <cuda_runtime.h>
#include <cuda_bf16.h>
#include <math.h>
#include <stdint.h>

#define BHN   16
#define LEN   2048
#define DIM   64
#define MRP   1024
#define QT    16
#define TRI   136
#define MSH   8.0f                      // fixed softmax shift (logits are O(1))
#define OUT_ELEMS ((size_t)BHN*LEN*DIM)

typedef unsigned long long u64;

// scratch
__device__ float    g_R[(size_t)BHN * LEN * MRP];        // rel logits
__device__ float    g_stats[(size_t)BHN * QT * LEN];     // partial exp-sums [bh][tj][row]
__device__ uint32_t g_VH[(size_t)BHN * DIM * (LEN/2)];   // split V hi, [bh][d][j] bf16x2
__device__ uint32_t g_VL[(size_t)BHN * DIM * (LEN/2)];   // split V lo

// ---------------- split fp32 -> (bf16 hi, bf16 lo) packed pairs ------------
__device__ __forceinline__ void split_pair(float x, float y,
                                           uint32_t &h, uint32_t &l) {
    __nv_bfloat16 hx = __float2bfloat16_rn(x), hy = __float2bfloat16_rn(y);
    float rx = x - __bfloat162float(hx), ry = y - __bfloat162float(hy);
    __nv_bfloat16 lx = __float2bfloat16_rn(rx), ly = __float2bfloat16_rn(ry);
    h = (uint32_t)__bfloat16_as_ushort(hx) | ((uint32_t)__bfloat16_as_ushort(hy) << 16);
    l = (uint32_t)__bfloat16_as_ushort(lx) | ((uint32_t)__bfloat16_as_ushort(ly) << 16);
}

// mma.sync m16n8k16 row.col f32.bf16.bf16.f32 (portable; no 'a'-target)
__device__ __forceinline__ void mma16816(float d[4], uint32_t a0, uint32_t a1,
                                         uint32_t a2, uint32_t a3,
                                         uint32_t b0, uint32_t b1) {
    asm volatile(
        "mma.sync.aligned.m16n8k16.row.col.f32.bf16.bf16.f32 "
        "{%0,%1,%2,%3}, {%4,%5,%6,%7}, {%8,%9}, {%0,%1,%2,%3};"
        : "+f"(d[0]), "+f"(d[1]), "+f"(d[2]), "+f"(d[3])
        : "r"(a0), "r"(a1), "r"(a2), "r"(a3), "r"(b0), "r"(b1));
}

__device__ __forceinline__ void tri_map(int t, int &ti, int &tj) {
    int i = (int)((sqrtf(8.0f * (float)t + 1.0f) - 1.0f) * 0.5f);
    while ((i + 1) * (i + 2) / 2 <= t) i++;
    while (i * (i + 1) / 2 > t) i--;
    ti = i; tj = t - i * (i + 1) / 2;
}

// smem strides (bf16 elems); frag LDS.32 conflict-free (bank = 4g+t distinct)
#define STQ 72

#define QK_AH 0
#define QK_AL (128*STQ)
#define QK_BH (2*128*STQ)
#define QK_BL (3*128*STQ)
#define QK_SMEM (4*128*STQ*2)            // 73728 bytes

// ---------------- zero the attention-output region -------------------------
__global__ void k_zero(float* __restrict__ O) {
    size_t i = ((size_t)blockIdx.x * 256 + threadIdx.x) * 4;
    *(float4*)(O + i) = make_float4(0.f, 0.f, 0.f, 0.f);
}

// ---------------- V pre-split: [bh][j][d] fp32 -> [bh][d][j] bf16 hi/lo ----
__global__ void __launch_bounds__(256) k_vsplit(const float* __restrict__ V) {
    __shared__ float tr[64][33];
    const int jc = blockIdx.x;           // 32-j chunk
    const int bh = blockIdx.y;
    const int tid = threadIdx.x;
    const float* Vb = V + ((size_t)bh * LEN + jc * 32) * DIM;
    #pragma unroll
    for (int rep = 0; rep < 2; rep++) {
        int f4 = tid + rep * 256;        // 0..511
        int jr = f4 >> 4;
        int d4 = (f4 & 15) * 4;
        float4 v = *(const float4*)(Vb + (size_t)jr * DIM + d4);
        tr[d4+0][jr] = v.x; tr[d4+1][jr] = v.y;
        tr[d4+2][jr] = v.z; tr[d4+3][jr] = v.w;
    }
    __syncthreads();
    #pragma unroll
    for (int rep = 0; rep < 4; rep++) {
        int oi = tid + rep * 256;        // 0..1023
        int d = oi >> 4, j2 = oi & 15;
        uint32_t h, l;
        split_pair(tr[d][j2*2], tr[d][j2*2+1], h, l);
        size_t gi = ((size_t)bh * DIM + d) * (LEN/2) + jc * 16 + j2;
        g_VH[gi] = h; g_VL[gi] = l;
    }
}

// ---------------------------------------------------------------------------
// 128x128 NT tile body (A[128x64] @ B[128x64]^T, split bf16, 3-product)
// ---------------------------------------------------------------------------
__device__ __forceinline__ void qk_body(const float* __restrict__ Ag,
                                        const float* __restrict__ Bg,
                                        uint16_t* sm, float acc[2][8][4]) {
    const int tid = threadIdx.x;
    uint32_t* AH = (uint32_t*)(sm + QK_AH);
    uint32_t* AL = (uint32_t*)(sm + QK_AL);
    uint32_t* BH = (uint32_t*)(sm + QK_BH);
    uint32_t* BL = (uint32_t*)(sm + QK_BL);
    #pragma unroll
    for (int it = 0; it < 8; it++) {
        int idx = tid + it * 256;
        int row = idx >> 4;
        int c4  = (idx & 15) * 4;
        int so  = (row * STQ + c4) >> 1;
        float4 va = *(const float4*)(Ag + (size_t)row * DIM + c4);
        uint32_t h, l;
        split_pair(va.x, va.y, h, l); AH[so] = h;     AL[so] = l;
        split_pair(va.z, va.w, h, l); AH[so + 1] = h; AL[so + 1] = l;
        float4 vb = *(const float4*)(Bg + (size_t)row * DIM + c4);
        split_pair(vb.x, vb.y, h, l); BH[so] = h;     BL[so] = l;
        split_pair(vb.z, vb.w, h, l); BH[so + 1] = h; BL[so + 1] = l;
    }
    __syncthreads();

    const int w = tid >> 5, lane = tid & 31;
    const int wr = w >> 1, wc = w & 1;
    const int g = lane >> 2, t = lane & 3;
    #pragma unroll
    for (int ks = 0; ks < 4; ks++) {
        const int k0 = ks * 16 + 2 * t;
        uint32_t ah[2][4], al[2][4];
        #pragma unroll
        for (int mi = 0; mi < 2; mi++) {
            int r = wr * 32 + mi * 16 + g;
            int o0 = (r * STQ + k0) >> 1, o1 = ((r + 8) * STQ + k0) >> 1;
            ah[mi][0] = AH[o0];     ah[mi][1] = AH[o1];
            ah[mi][2] = AH[o0 + 4]; ah[mi][3] = AH[o1 + 4];
            al[mi][0] = AL[o0];     al[mi][1] = AL[o1];
            al[mi][2] = AL[o0 + 4]; al[mi][3] = AL[o1 + 4];
        }
        #pragma unroll
        for (int ni = 0; ni < 8; ni++) {
            int n = wc * 64 + ni * 8 + g;
            int ob = (n * STQ + k0) >> 1;
            uint32_t bh0 = BH[ob], bh1 = BH[ob + 4];
            uint32_t bl0 = BL[ob], bl1 = BL[ob + 4];
            #pragma unroll
            for (int mi = 0; mi < 2; mi++) {
                mma16816(acc[mi][ni], ah[mi][0], ah[mi][1], ah[mi][2], ah[mi][3], bh0, bh1);
                mma16816(acc[mi][ni], ah[mi][0], ah[mi][1], ah[mi][2], ah[mi][3], bl0, bl1);
                mma16816(acc[mi][ni], al[mi][0], al[mi][1], al[mi][2], al[mi][3], bh0, bh1);
            }
        }
    }
}

// ---------------- R = Q @ embed^T (pruned: tiles never read are skipped) ---
__global__ void __launch_bounds__(256, 2) k_relgemm(const float* __restrict__ Q,
                                                    const float* __restrict__ E) {
    const int rt = blockIdx.x, ct = blockIdx.y, bh = blockIdx.z;
    if (rt + ct <= 6) return;            // R[q,e] read only where e >= 1023-q
    extern __shared__ uint16_t smq[];
    float acc[2][8][4];
    #pragma unroll
    for (int a = 0; a < 2; a++)
        #pragma unroll
        for (int b = 0; b < 8; b++)
            #pragma unroll
            for (int c = 0; c < 4; c++) acc[a][b][c] = 0.f;
    qk_body(Q + ((size_t)bh * LEN + rt * 128) * DIM,
            E + (size_t)(ct * 128) * DIM, smq, acc);

    const int tid = threadIdx.x, w = tid >> 5, lane = tid & 31;
    const int wr = w >> 1, wc = w & 1, g = lane >> 2, t = lane & 3;
    #pragma unroll
    for (int mi = 0; mi < 2; mi++) {
        int q0 = rt * 128 + wr * 32 + mi * 16 + g;
        float* R0 = g_R + ((size_t)bh * LEN + q0) * MRP + ct * 128;
        float* R1 = R0 + 8 * MRP;
        #pragma unroll
        for (int ni = 0; ni < 8; ni++) {
            int c = wc * 64 + ni * 8 + 2 * t;
            *(float2*)(R0 + c) = make_float2(acc[mi][ni][0], acc[mi][ni][1]);
            *(float2*)(R1 + c) = make_float2(acc[mi][ni][2], acc[mi][ni][3]);
        }
    }
}

// ---------------- E = exp(Q@K^T + rel - 8), + partial exp-sums -------------
__global__ void __launch_bounds__(256, 2) k_qk(const float* __restrict__ Q,
                                               const float* __restrict__ Kt,
                                               float* __restrict__ Wt) {
    extern __shared__ uint16_t smq[];
    __shared__ float s_part[2][128];
    int ti, tj; tri_map(blockIdx.x, ti, tj);
    const int bh = blockIdx.y;
    float acc[2][8][4];
    #pragma unroll
    for (int a = 0; a < 2; a++)
        #pragma unroll
        for (int b = 0; b < 8; b++)
            #pragma unroll
            for (int c = 0; c < 4; c++) acc[a][b][c] = 0.f;
    qk_body(Q + ((size_t)bh * LEN + ti * 128) * DIM,
            Kt + ((size_t)bh * LEN + tj * 128) * DIM, smq, acc);

    const int tid = threadIdx.x, w = tid >> 5, lane = tid & 31;
    const int wr = w >> 1, wc = w & 1, g = lane >> 2, t = lane & 3;
    #pragma unroll
    for (int mi = 0; mi < 2; mi++) {
        #pragma unroll
        for (int rh = 0; rh < 2; rh++) {
            const int rloc = wr * 32 + mi * 16 + rh * 8 + g;
            const int q0 = ti * 128 + rloc;
            const float* Rrow = g_R + ((size_t)bh * LEN + q0) * MRP;
            float* Wrow = Wt + ((size_t)bh * LEN + q0) * LEN + tj * 128;
            float ssum = 0.f;
            #pragma unroll
            for (int ni = 0; ni < 8; ni++) {
                int c = wc * 64 + ni * 8 + 2 * t;
                int j = tj * 128 + c;
                int rp = j - q0 + (MRP - 1);
                float r0 = (rp >= 0 && rp < MRP) ? Rrow[rp] : 0.f;
                int rp1 = rp + 1;
                float r1 = (rp1 >= 0 && rp1 < MRP) ? Rrow[rp1] : 0.f;
                float x0 = acc[mi][ni][2 * rh + 0] + r0;
                float x1 = acc[mi][ni][2 * rh + 1] + r1;
                float e0 = (j     <= q0) ? __expf(x0 - MSH) : 0.f;
                float e1 = (j + 1 <= q0) ? __expf(x1 - MSH) : 0.f;
                *(float2*)(Wrow + c) = make_float2(e0, e1);
                ssum += e0 + e1;
            }
            ssum += __shfl_xor_sync(0xffffffffu, ssum, 1);
            ssum += __shfl_xor_sync(0xffffffffu, ssum, 2);
            if (t == 0) s_part[wc][rloc] = ssum;
        }
    }
    __syncthreads();
    if (tid < 128)
        g_stats[((size_t)bh * QT + tj) * LEN + ti * 128 + tid] =
            s_part[0][tid] + s_part[1][tid];
}

// ---------------- fused normalize + O = W @ V (balanced split-K) -----------
// Grid x = 24: s<8 -> full band ti=s; s>=8 -> half-band of ti=8+(s-8)/2.
__global__ void __launch_bounds__(256) k_smpv(float* __restrict__ Wt,
                                              float* __restrict__ O) {
    __shared__ float rowInv[128];
    __shared__ uint32_t VHs[64 * 68], VLs[64 * 68];
    const int s = blockIdx.x, bh = blockIdx.y;
    int ti, tj0, tj1, zt0, ztstep;
    if (s < 8) {
        ti = s; tj0 = 0; tj1 = ti + 1; zt0 = ti + 1; ztstep = 1;
    } else {
        int k2 = s - 8; ti = 8 + (k2 >> 1);
        int cnt = ti + 1, first = (cnt + 1) >> 1;
        if (k2 & 1) { tj0 = first; tj1 = cnt; } else { tj0 = 0; tj1 = first; }
        zt0 = ti + 1 + (k2 & 1); ztstep = 2;
    }
    const int tid = threadIdx.x, w = tid >> 5, lane = tid & 31;
    const int g = lane >> 2, t = lane & 3;

    if (tid < 128) {
        const int row = ti * 128 + tid;
        float S = 0.f;
        for (int tj = 0; tj <= ti; tj++)
            S += g_stats[((size_t)bh * QT + tj) * LEN + row];
        rowInv[tid] = 1.0f / S;
    }

    float acc[8][4];
    #pragma unroll
    for (int b = 0; b < 8; b++)
        #pragma unroll
        for (int c = 0; c < 4; c++) acc[b][c] = 0.f;

    const int rloc0 = w * 16 + g;
    float* W0 = Wt + ((size_t)bh * LEN + ti * 128 + rloc0) * LEN;
    float* W1 = W0 + 8 * LEN;

    for (int tj = tj0; tj < tj1; tj++) {
        __syncthreads();                     // V smem reuse + (first) rowInv
        #pragma unroll
        for (int rep = 0; rep < 4; rep++) {  // copy pre-split V tile
            int li = tid + rep * 256;
            int d = li >> 4, j4 = (li & 15) * 4;
            size_t gi = ((size_t)bh * DIM + d) * (LEN/2) + tj * 64 + j4;
            *(uint4*)&VHs[d * 68 + j4] = *(const uint4*)&g_VH[gi];
            *(uint4*)&VLs[d * 68 + j4] = *(const uint4*)&g_VL[gi];
        }
        __syncthreads();

        const float I0 = rowInv[rloc0], I1 = rowInv[rloc0 + 8];
        #pragma unroll
        for (int ks = 0; ks < 8; ks++) {
            const int c0 = tj * 128 + ks * 16 + 2 * t;
            float2 e00 = *(const float2*)(W0 + c0);
            float2 e01 = *(const float2*)(W0 + c0 + 8);
            float2 e10 = *(const float2*)(W1 + c0);
            float2 e11 = *(const float2*)(W1 + c0 + 8);
            float p00x = e00.x * I0, p00y = e00.y * I0;
            float p01x = e01.x * I0, p01y = e01.y * I0;
            float p10x = e10.x * I1, p10y = e10.y * I1;
            float p11x = e11.x * I1, p11y = e11.y * I1;
            *(float2*)(W0 + c0)     = make_float2(p00x, p00y);
            *(float2*)(W0 + c0 + 8) = make_float2(p01x, p01y);
            *(float2*)(W1 + c0)     = make_float2(p10x, p10y);
            *(float2*)(W1 + c0 + 8) = make_float2(p11x, p11y);
            uint32_t ah[4], al[4];
            split_pair(p00x, p00y, ah[0], al[0]);
            split_pair(p10x, p10y, ah[1], al[1]);
            split_pair(p01x, p01y, ah[2], al[2]);
            split_pair(p11x, p11y, ah[3], al[3]);
            #pragma unroll
            for (int ni = 0; ni < 8; ni++) {
                int ob = (ni * 8 + g) * 68 + ks * 8 + t;
                uint32_t bh0 = VHs[ob], bh1 = VHs[ob + 4];
                uint32_t bl0 = VLs[ob], bl1 = VLs[ob + 4];
                mma16816(acc[ni], ah[0], ah[1], ah[2], ah[3], bh0, bh1);
                mma16816(acc[ni], ah[0], ah[1], ah[2], ah[3], bl0, bl1);
                mma16816(acc[ni], al[0], al[1], al[2], al[3], bh0, bh1);
            }
        }
    }

    // atomic-accumulate O (O pre-zeroed)
    float* O0 = O + ((size_t)bh * LEN + ti * 128 + rloc0) * DIM;
    float* O1 = O0 + 8 * DIM;
    #pragma unroll
    for (int ni = 0; ni < 8; ni++) {
        int c = ni * 8 + 2 * t;
        atomicAdd(O0 + c,     acc[ni][0]);
        atomicAdd(O0 + c + 1, acc[ni][1]);
        atomicAdd(O1 + c,     acc[ni][2]);
        atomicAdd(O1 + c + 1, acc[ni][3]);
    }

    // distributed zero-fill of this band's strictly-upper tiles
    for (int tz = zt0; tz < QT; tz += ztstep) {
        float* Zb = Wt + ((size_t)bh * LEN + ti * 128) * LEN + tz * 128;
        #pragma unroll
        for (int rep = 0; rep < 16; rep++) {
            int idx = tid + rep * 256;       // 4096 float4
            int rr = idx >> 5, cc = (idx & 31) * 4;
            *(float4*)(Zb + (size_t)rr * LEN + cc) = make_float4(0.f, 0.f, 0.f, 0.f);
        }
    }
}

// ---------------------------------------------------------------------------
extern "C" void kernel_launch(void* const* d_in, const int* in_sizes, int n_in,
                              void* d_out, int out_size) {
    const float* q   = (const float*)d_in[0];
    const float* k   = (const float*)d_in[1];
    const float* v   = (const float*)d_in[2];
    const float* rel = (const float*)d_in[3];

    float* out = (float*)d_out;
    float* Wt  = out + OUT_ELEMS;

    cudaFuncSetAttribute(k_relgemm, cudaFuncAttributeMaxDynamicSharedMemorySize, QK_SMEM);
    cudaFuncSetAttribute(k_qk,      cudaFuncAttributeMaxDynamicSharedMemorySize, QK_SMEM);

    k_zero<<<(unsigned)(OUT_ELEMS / 1024), 256>>>(out);

    dim3 gv(LEN / 32, BHN);
    k_vsplit<<<gv, 256>>>(v);

    dim3 g0(QT, MRP / 128, BHN);
    k_relgemm<<<g0, 256, QK_SMEM>>>(q, rel);

    dim3 g1(TRI, BHN);
    k_qk<<<g1, 256, QK_SMEM>>>(q, k, Wt);

    dim3 g2(24, BHN);
    k_smpv<<<g2, 256>>>(Wt, out);
}

// round 11
// speedup vs baseline: 1.5027x; 1.5027x over previous
#include <cuda_runtime.h>
#include <cuda_bf16.h>
#include <math.h>
#include <stdint.h>

#define BHN   16
#define LEN   2048
#define DIM   64
#define MRP   1024
#define QT    16
#define TRI   136
#define OUT_ELEMS ((size_t)BHN*LEN*DIM)

typedef unsigned long long u64;

// scratch
__device__ float    g_R[(size_t)BHN * LEN * MRP];        // rel logits
__device__ uint32_t g_VH[(size_t)BHN * DIM * (LEN/2)];   // split V hi, [bh][d][j] bf16x2
__device__ uint32_t g_VL[(size_t)BHN * DIM * (LEN/2)];   // split V lo

// ---------------- split fp32 -> (bf16 hi, bf16 lo) packed pairs ------------
__device__ __forceinline__ void split_pair(float x, float y,
                                           uint32_t &h, uint32_t &l) {
    __nv_bfloat16 hx = __float2bfloat16_rn(x), hy = __float2bfloat16_rn(y);
    float rx = x - __bfloat162float(hx), ry = y - __bfloat162float(hy);
    __nv_bfloat16 lx = __float2bfloat16_rn(rx), ly = __float2bfloat16_rn(ry);
    h = (uint32_t)__bfloat16_as_ushort(hx) | ((uint32_t)__bfloat16_as_ushort(hy) << 16);
    l = (uint32_t)__bfloat16_as_ushort(lx) | ((uint32_t)__bfloat16_as_ushort(ly) << 16);
}

// mma.sync m16n8k16 row.col f32.bf16.bf16.f32 (portable; no 'a'-target)
__device__ __forceinline__ void mma16816(float d[4], uint32_t a0, uint32_t a1,
                                         uint32_t a2, uint32_t a3,
                                         uint32_t b0, uint32_t b1) {
    asm volatile(
        "mma.sync.aligned.m16n8k16.row.col.f32.bf16.bf16.f32 "
        "{%0,%1,%2,%3}, {%4,%5,%6,%7}, {%8,%9}, {%0,%1,%2,%3};"
        : "+f"(d[0]), "+f"(d[1]), "+f"(d[2]), "+f"(d[3])
        : "r"(a0), "r"(a1), "r"(a2), "r"(a3), "r"(b0), "r"(b1));
}

__device__ __forceinline__ void tri_map(int t, int &ti, int &tj) {
    int i = (int)((sqrtf(8.0f * (float)t + 1.0f) - 1.0f) * 0.5f);
    while ((i + 1) * (i + 2) / 2 <= t) i++;
    while (i * (i + 1) / 2 > t) i--;
    ti = i; tj = t - i * (i + 1) / 2;
}

// smem strides (bf16 elems); frag LDS.32 conflict-free (bank = 4g+t distinct)
#define STQ 72
#define STP 136

// qk/relgemm smem map (bf16 units): AH[128][72], AL, BH, BL
#define QK_AH 0
#define QK_AL (128*STQ)
#define QK_BH (2*128*STQ)
#define QK_BL (3*128*STQ)
#define QK_SMEM (4*128*STQ*2)            // 73728 bytes -> 3 CTAs/SM fit

// pv smem map: WH[128][136], WL, VH[64][136], VL
#define PV_WH 0
#define PV_WL (128*STP)
#define PV_VH (2*128*STP)
#define PV_VL (2*128*STP + 64*STP)
#define PV_SMEM ((2*128*STP + 2*64*STP)*2)  // 104448 bytes

// ---------------- zero the attention-output region -------------------------
__global__ void k_zero(float* __restrict__ O) {
    size_t i = ((size_t)blockIdx.x * 256 + threadIdx.x) * 4;
    *(float4*)(O + i) = make_float4(0.f, 0.f, 0.f, 0.f);
}

// ---------------- V pre-split: [bh][j][d] fp32 -> [bh][d][j] bf16 hi/lo ----
__global__ void __launch_bounds__(256) k_vsplit(const float* __restrict__ V) {
    __shared__ float tr[64][33];
    const int jc = blockIdx.x;           // 32-j chunk
    const int bh = blockIdx.y;
    const int tid = threadIdx.x;
    const float* Vb = V + ((size_t)bh * LEN + jc * 32) * DIM;
    #pragma unroll
    for (int rep = 0; rep < 2; rep++) {
        int f4 = tid + rep * 256;        // 0..511
        int jr = f4 >> 4;
        int d4 = (f4 & 15) * 4;
        float4 v = *(const float4*)(Vb + (size_t)jr * DIM + d4);
        tr[d4+0][jr] = v.x; tr[d4+1][jr] = v.y;
        tr[d4+2][jr] = v.z; tr[d4+3][jr] = v.w;
    }
    __syncthreads();
    #pragma unroll
    for (int rep = 0; rep < 4; rep++) {
        int oi = tid + rep * 256;        // 0..1023
        int d = oi >> 4, j2 = oi & 15;
        uint32_t h, l;
        split_pair(tr[d][j2*2], tr[d][j2*2+1], h, l);
        size_t gi = ((size_t)bh * DIM + d) * (LEN/2) + jc * 16 + j2;
        g_VH[gi] = h; g_VL[gi] = l;
    }
}

// ---------------------------------------------------------------------------
// 128x128 NT tile body (A[128x64] @ B[128x64]^T, split bf16, 3-product)
// ---------------------------------------------------------------------------
__device__ __forceinline__ void qk_body(const float* __restrict__ Ag,
                                        const float* __restrict__ Bg,
                                        uint16_t* sm, float acc[2][8][4]) {
    const int tid = threadIdx.x;
    uint32_t* AH = (uint32_t*)(sm + QK_AH);
    uint32_t* AL = (uint32_t*)(sm + QK_AL);
    uint32_t* BH = (uint32_t*)(sm + QK_BH);
    uint32_t* BL = (uint32_t*)(sm + QK_BL);
    #pragma unroll
    for (int it = 0; it < 8; it++) {
        int idx = tid + it * 256;
        int row = idx >> 4;
        int c4  = (idx & 15) * 4;
        int so  = (row * STQ + c4) >> 1;
        float4 va = *(const float4*)(Ag + (size_t)row * DIM + c4);
        uint32_t h, l;
        split_pair(va.x, va.y, h, l); AH[so] = h;     AL[so] = l;
        split_pair(va.z, va.w, h, l); AH[so + 1] = h; AL[so + 1] = l;
        float4 vb = *(const float4*)(Bg + (size_t)row * DIM + c4);
        split_pair(vb.x, vb.y, h, l); BH[so] = h;     BL[so] = l;
        split_pair(vb.z, vb.w, h, l); BH[so + 1] = h; BL[so + 1] = l;
    }
    __syncthreads();

    const int w = tid >> 5, lane = tid & 31;
    const int wr = w >> 1, wc = w & 1;
    const int g = lane >> 2, t = lane & 3;
    #pragma unroll
    for (int ks = 0; ks < 4; ks++) {
        const int k0 = ks * 16 + 2 * t;
        uint32_t ah[2][4], al[2][4];
        #pragma unroll
        for (int mi = 0; mi < 2; mi++) {
            int r = wr * 32 + mi * 16 + g;
            int o0 = (r * STQ + k0) >> 1, o1 = ((r + 8) * STQ + k0) >> 1;
            ah[mi][0] = AH[o0];     ah[mi][1] = AH[o1];
            ah[mi][2] = AH[o0 + 4]; ah[mi][3] = AH[o1 + 4];
            al[mi][0] = AL[o0];     al[mi][1] = AL[o1];
            al[mi][2] = AL[o0 + 4]; al[mi][3] = AL[o1 + 4];
        }
        #pragma unroll
        for (int ni = 0; ni < 8; ni++) {
            int n = wc * 64 + ni * 8 + g;
            int ob = (n * STQ + k0) >> 1;
            uint32_t bh0 = BH[ob], bh1 = BH[ob + 4];
            uint32_t bl0 = BL[ob], bl1 = BL[ob + 4];
            #pragma unroll
            for (int mi = 0; mi < 2; mi++) {
                mma16816(acc[mi][ni], ah[mi][0], ah[mi][1], ah[mi][2], ah[mi][3], bh0, bh1);
                mma16816(acc[mi][ni], ah[mi][0], ah[mi][1], ah[mi][2], ah[mi][3], bl0, bl1);
                mma16816(acc[mi][ni], al[mi][0], al[mi][1], al[mi][2], al[mi][3], bh0, bh1);
            }
        }
    }
}

// ---------------- R = Q @ embed^T (pruned; 3 CTAs/SM) ----------------------
__global__ void __launch_bounds__(256, 3) k_relgemm(const float* __restrict__ Q,
                                                    const float* __restrict__ E) {
    const int rt = blockIdx.x, ct = blockIdx.y, bh = blockIdx.z;
    if (rt + ct <= 6) return;            // R[q,e] read only where e >= 1023-q
    extern __shared__ uint16_t smq[];
    float acc[2][8][4];
    #pragma unroll
    for (int a = 0; a < 2; a++)
        #pragma unroll
        for (int b = 0; b < 8; b++)
            #pragma unroll
            for (int c = 0; c < 4; c++) acc[a][b][c] = 0.f;
    qk_body(Q + ((size_t)bh * LEN + rt * 128) * DIM,
            E + (size_t)(ct * 128) * DIM, smq, acc);

    const int tid = threadIdx.x, w = tid >> 5, lane = tid & 31;
    const int wr = w >> 1, wc = w & 1, g = lane >> 2, t = lane & 3;
    #pragma unroll
    for (int mi = 0; mi < 2; mi++) {
        int q0 = rt * 128 + wr * 32 + mi * 16 + g;
        float* R0 = g_R + ((size_t)bh * LEN + q0) * MRP + ct * 128;
        float* R1 = R0 + 8 * MRP;
        #pragma unroll
        for (int ni = 0; ni < 8; ni++) {
            int c = wc * 64 + ni * 8 + 2 * t;
            *(float2*)(R0 + c) = make_float2(acc[mi][ni][0], acc[mi][ni][1]);
            *(float2*)(R1 + c) = make_float2(acc[mi][ni][2], acc[mi][ni][3]);
        }
    }
}

// ---------------- S = Q @ K^T + rel (lower-tri tiles; 3 CTAs/SM) -----------
__global__ void __launch_bounds__(256, 3) k_qk(const float* __restrict__ Q,
                                               const float* __restrict__ Kt,
                                               float* __restrict__ Wt) {
    extern __shared__ uint16_t smq[];
    int ti, tj; tri_map(blockIdx.x, ti, tj);
    const int bh = blockIdx.y;
    float acc[2][8][4];
    #pragma unroll
    for (int a = 0; a < 2; a++)
        #pragma unroll
        for (int b = 0; b < 8; b++)
            #pragma unroll
            for (int c = 0; c < 4; c++) acc[a][b][c] = 0.f;
    qk_body(Q + ((size_t)bh * LEN + ti * 128) * DIM,
            Kt + ((size_t)bh * LEN + tj * 128) * DIM, smq, acc);

    const int tid = threadIdx.x, w = tid >> 5, lane = tid & 31;
    const int wr = w >> 1, wc = w & 1, g = lane >> 2, t = lane & 3;
    #pragma unroll
    for (int mi = 0; mi < 2; mi++) {
        #pragma unroll
        for (int rh = 0; rh < 2; rh++) {
            int q0 = ti * 128 + wr * 32 + mi * 16 + g + rh * 8;
            const float* Rrow = g_R + ((size_t)bh * LEN + q0) * MRP;
            float* Wrow = Wt + ((size_t)bh * LEN + q0) * LEN + tj * 128;
            #pragma unroll
            for (int ni = 0; ni < 8; ni++) {
                int c = wc * 64 + ni * 8 + 2 * t;
                int j = tj * 128 + c;
                int rp = j - q0 + (MRP - 1);
                float r0 = (rp >= 0 && rp < MRP) ? Rrow[rp] : 0.f;
                int rp1 = rp + 1;
                float r1 = (rp1 >= 0 && rp1 < MRP) ? Rrow[rp1] : 0.f;
                float x0 = acc[mi][ni][2 * rh + 0] + r0;
                float x1 = acc[mi][ni][2 * rh + 1] + r1;
                *(float2*)(Wrow + c) = make_float2(x0, x1);
            }
        }
    }
}

// ---------------- row softmax ----------------------------------------------
__global__ void __launch_bounds__(256) k_softmax(float* __restrict__ Wt) {
    const int q  = blockIdx.x & (LEN - 1);
    const int bh = blockIdx.x >> 11;
    float* Wrow = Wt + ((size_t)bh * LEN + q) * LEN;
    const int tid = threadIdx.x;
    const int ja = tid * 4, jb = 1024 + tid * 4;
    float4 wa = make_float4(-3e38f, -3e38f, -3e38f, -3e38f), wb = wa;
    if (ja <= q) wa = *(const float4*)(Wrow + ja);
    if (jb <= q) wb = *(const float4*)(Wrow + jb);
    float va[4] = {wa.x, wa.y, wa.z, wa.w};
    float vb[4] = {wb.x, wb.y, wb.z, wb.w};

    float m = -3.0e38f;
    #pragma unroll
    for (int c = 0; c < 4; c++) {
        if (ja + c <= q) m = fmaxf(m, va[c]);
        if (jb + c <= q) m = fmaxf(m, vb[c]);
    }
    __shared__ float red[9];
    #pragma unroll
    for (int o = 16; o > 0; o >>= 1) m = fmaxf(m, __shfl_xor_sync(0xffffffffu, m, o));
    if ((tid & 31) == 0) red[tid >> 5] = m;
    __syncthreads();
    if (tid == 0) {
        float x = red[0];
        #pragma unroll
        for (int w = 1; w < 8; w++) x = fmaxf(x, red[w]);
        red[8] = x;
    }
    __syncthreads();
    const float bm = red[8];

    float ea[4], eb[4], s = 0.f;
    #pragma unroll
    for (int c = 0; c < 4; c++) {
        ea[c] = (ja + c <= q) ? __expf(va[c] - bm) : 0.f;
        eb[c] = (jb + c <= q) ? __expf(vb[c] - bm) : 0.f;
        s += ea[c] + eb[c];
    }
    __syncthreads();
    #pragma unroll
    for (int o = 16; o > 0; o >>= 1) s += __shfl_xor_sync(0xffffffffu, s, o);
    if ((tid & 31) == 0) red[tid >> 5] = s;
    __syncthreads();
    if (tid == 0) {
        float x = red[0];
        #pragma unroll
        for (int w = 1; w < 8; w++) x += red[w];
        red[8] = x;
    }
    __syncthreads();
    const float inv = 1.0f / red[8];
    *(float4*)(Wrow + ja) = make_float4(ea[0]*inv, ea[1]*inv, ea[2]*inv, ea[3]*inv);
    *(float4*)(Wrow + jb) = make_float4(eb[0]*inv, eb[1]*inv, eb[2]*inv, eb[3]*inv);
}

// ---------------- O = W @ V (split-K, register acc, atomic epilogue) -------
__global__ void __launch_bounds__(256, 2) k_pv(const float* __restrict__ Wt,
                                               const float* __restrict__ V,
                                               float* __restrict__ O) {
    extern __shared__ uint16_t smp[];
    const int s = blockIdx.x, bh = blockIdx.y;
    int ti, tj0, tj1;
    if (s < 8) { ti = s; tj0 = 0; tj1 = ti + 1; }
    else {
        int k2 = s - 8; ti = 8 + (k2 >> 1);
        int cnt = ti + 1, first = (cnt + 1) >> 1;
        if (k2 & 1) { tj0 = first; tj1 = cnt; } else { tj0 = 0; tj1 = first; }
    }
    uint32_t* WH = (uint32_t*)(smp + PV_WH);
    uint32_t* WL = (uint32_t*)(smp + PV_WL);
    uint32_t* VH = (uint32_t*)(smp + PV_VH);
    uint32_t* VL = (uint32_t*)(smp + PV_VL);

    const int tid = threadIdx.x, w = tid >> 5, lane = tid & 31;
    const int wr = w >> 1, wc = w & 1, g = lane >> 2, t = lane & 3;

    float acc[2][4][4];
    #pragma unroll
    for (int a = 0; a < 2; a++)
        #pragma unroll
        for (int b = 0; b < 4; b++)
            #pragma unroll
            for (int c = 0; c < 4; c++) acc[a][b][c] = 0.f;

    for (int tj = tj0; tj < tj1; tj++) {
        const float* Wg = Wt + ((size_t)bh * LEN + ti * 128) * LEN + tj * 128;
        __syncthreads();
        #pragma unroll
        for (int it = 0; it < 16; it++) {       // W: 128x128 -> 4096 float4
            int idx = tid + it * 256;
            int row = idx >> 5;
            int c4  = (idx & 31) * 4;
            int so  = (row * STP + c4) >> 1;
            float4 vv = *(const float4*)(Wg + (size_t)row * LEN + c4);
            uint32_t h, l;
            split_pair(vv.x, vv.y, h, l); WH[so] = h;     WL[so] = l;
            split_pair(vv.z, vv.w, h, l); WH[so + 1] = h; WL[so + 1] = l;
        }
        #pragma unroll
        for (int it = 0; it < 4; it++) {        // V: pre-split copy (1024 uint4)
            int li = tid + it * 256;
            int d = li >> 4, j4 = (li & 15) * 4;
            size_t gi = ((size_t)bh * DIM + d) * (LEN/2) + tj * 64 + j4;
            *(uint4*)&VH[d * 68 + j4] = *(const uint4*)&g_VH[gi];
            *(uint4*)&VL[d * 68 + j4] = *(const uint4*)&g_VL[gi];
        }
        __syncthreads();

        #pragma unroll
        for (int ks = 0; ks < 8; ks++) {
            const int k0 = ks * 16 + 2 * t;
            uint32_t ah[2][4], al[2][4];
            #pragma unroll
            for (int mi = 0; mi < 2; mi++) {
                int r = wr * 32 + mi * 16 + g;
                int o0 = (r * STP + k0) >> 1, o1 = ((r + 8) * STP + k0) >> 1;
                ah[mi][0] = WH[o0];     ah[mi][1] = WH[o1];
                ah[mi][2] = WH[o0 + 4]; ah[mi][3] = WH[o1 + 4];
                al[mi][0] = WL[o0];     al[mi][1] = WL[o1];
                al[mi][2] = WL[o0 + 4]; al[mi][3] = WL[o1 + 4];
            }
            #pragma unroll
            for (int ni = 0; ni < 4; ni++) {
                int n = wc * 32 + ni * 8 + g;
                int ob = (n * STP + k0) >> 1;
                uint32_t bh0 = VH[ob], bh1 = VH[ob + 4];
                uint32_t bl0 = VL[ob], bl1 = VL[ob + 4];
                #pragma unroll
                for (int mi = 0; mi < 2; mi++) {
                    mma16816(acc[mi][ni], ah[mi][0], ah[mi][1], ah[mi][2], ah[mi][3], bh0, bh1);
                    mma16816(acc[mi][ni], ah[mi][0], ah[mi][1], ah[mi][2], ah[mi][3], bl0, bl1);
                    mma16816(acc[mi][ni], al[mi][0], al[mi][1], al[mi][2], al[mi][3], bh0, bh1);
                }
            }
        }
    }

    #pragma unroll
    for (int mi = 0; mi < 2; mi++) {
        #pragma unroll
        for (int rh = 0; rh < 2; rh++) {
            int row = ti * 128 + wr * 32 + mi * 16 + g + rh * 8;
            float* orow = O + ((size_t)bh * LEN + row) * DIM;
            #pragma unroll
            for (int ni = 0; ni < 4; ni++) {
                int c = wc * 32 + ni * 8 + 2 * t;
                atomicAdd(orow + c,     acc[mi][ni][2 * rh + 0]);
                atomicAdd(orow + c + 1, acc[mi][ni][2 * rh + 1]);
            }
        }
    }
}

// ---------------------------------------------------------------------------
extern "C" void kernel_launch(void* const* d_in, const int* in_sizes, int n_in,
                              void* d_out, int out_size) {
    const float* q   = (const float*)d_in[0];
    const float* k   = (const float*)d_in[1];
    const float* v   = (const float*)d_in[2];
    const float* rel = (const float*)d_in[3];

    float* out = (float*)d_out;
    float* Wt  = out + OUT_ELEMS;

    cudaFuncSetAttribute(k_relgemm, cudaFuncAttributeMaxDynamicSharedMemorySize, QK_SMEM);
    cudaFuncSetAttribute(k_qk,      cudaFuncAttributeMaxDynamicSharedMemorySize, QK_SMEM);
    cudaFuncSetAttribute(k_pv,      cudaFuncAttributeMaxDynamicSharedMemorySize, PV_SMEM);

    k_zero<<<(unsigned)(OUT_ELEMS / 1024), 256>>>(out);

    dim3 gv(LEN / 32, BHN);
    k_vsplit<<<gv, 256>>>(v);

    dim3 g0(QT, MRP / 128, BHN);
    k_relgemm<<<g0, 256, QK_SMEM>>>(q, rel);

    dim3 g1(TRI, BHN);
    k_qk<<<g1, 256, QK_SMEM>>>(q, k, Wt);

    k_softmax<<<BHN * LEN, 256>>>(Wt);

    dim3 g2(24, BHN);
    k_pv<<<g2, 256, PV_SMEM>>>(Wt, v, out);
}

// round 15
// speedup vs baseline: 1.6465x; 1.0957x over previous
#include <cuda_runtime.h>
#include <cuda_bf16.h>
#include <math.h>
#include <stdint.h>

#define BHN   16
#define LEN   2048
#define DIM   64
#define MRP   1024
#define QT    16
#define TRI   136
#define OUT_ELEMS ((size_t)BHN*LEN*DIM)

typedef unsigned long long u64;

// scratch
__device__ float    g_R[(size_t)BHN * LEN * MRP];        // rel logits
__device__ uint32_t g_QH[(size_t)BHN * LEN * (DIM/2)];   // split Q hi (bf16x2)
__device__ uint32_t g_QL[(size_t)BHN * LEN * (DIM/2)];
__device__ uint32_t g_KH[(size_t)BHN * LEN * (DIM/2)];
__device__ uint32_t g_KL[(size_t)BHN * LEN * (DIM/2)];
__device__ uint32_t g_EH[(size_t)MRP * (DIM/2)];         // split embed
__device__ uint32_t g_EL[(size_t)MRP * (DIM/2)];
__device__ uint32_t g_VH[(size_t)BHN * DIM * (LEN/2)];   // split V^T [bh][d][j]
__device__ uint32_t g_VL[(size_t)BHN * DIM * (LEN/2)];

// ---------------- split fp32 -> (bf16 hi, bf16 lo) packed pairs ------------
__device__ __forceinline__ void split_pair(float x, float y,
                                           uint32_t &h, uint32_t &l) {
    __nv_bfloat16 hx = __float2bfloat16_rn(x), hy = __float2bfloat16_rn(y);
    float rx = x - __bfloat162float(hx), ry = y - __bfloat162float(hy);
    __nv_bfloat16 lx = __float2bfloat16_rn(rx), ly = __float2bfloat16_rn(ry);
    h = (uint32_t)__bfloat16_as_ushort(hx) | ((uint32_t)__bfloat16_as_ushort(hy) << 16);
    l = (uint32_t)__bfloat16_as_ushort(lx) | ((uint32_t)__bfloat16_as_ushort(ly) << 16);
}

// mma.sync m16n8k16 row.col f32.bf16.bf16.f32 (portable; no 'a'-target)
__device__ __forceinline__ void mma16816(float d[4], uint32_t a0, uint32_t a1,
                                         uint32_t a2, uint32_t a3,
                                         uint32_t b0, uint32_t b1) {
    asm volatile(
        "mma.sync.aligned.m16n8k16.row.col.f32.bf16.bf16.f32 "
        "{%0,%1,%2,%3}, {%4,%5,%6,%7}, {%8,%9}, {%0,%1,%2,%3};"
        : "+f"(d[0]), "+f"(d[1]), "+f"(d[2]), "+f"(d[3])
        : "r"(a0), "r"(a1), "r"(a2), "r"(a3), "r"(b0), "r"(b1));
}

__device__ __forceinline__ void tri_map(int t, int &ti, int &tj) {
    int i = (int)((sqrtf(8.0f * (float)t + 1.0f) - 1.0f) * 0.5f);
    while ((i + 1) * (i + 2) / 2 <= t) i++;
    while (i * (i + 1) / 2 > t) i--;
    ti = i; tj = t - i * (i + 1) / 2;
}

// smem strides (bf16 elems); frag LDS.32 conflict-free (bank = 4g+t distinct)
#define STQ 72
#define STP 136

#define QK_AH 0
#define QK_AL (128*STQ)
#define QK_BH (2*128*STQ)
#define QK_BL (3*128*STQ)
#define QK_SMEM (4*128*STQ*2)            // 73728 bytes

#define PV_WH 0
#define PV_WL (128*STP)
#define PV_VH (2*128*STP)
#define PV_VL (2*128*STP + 64*STP)
#define PV_SMEM ((2*128*STP + 2*64*STP)*2)  // 104448 bytes

// ---------------- zero the attention-output region -------------------------
__global__ void k_zero(float* __restrict__ O) {
    size_t i = ((size_t)blockIdx.x * 256 + threadIdx.x) * 4;
    *(float4*)(O + i) = make_float4(0.f, 0.f, 0.f, 0.f);
}

// ---------------- pre-split a row-major [rows][64] fp32 tensor -------------
__global__ void __launch_bounds__(256) k_presplit(const float* __restrict__ src,
                                                  uint32_t* __restrict__ dH,
                                                  uint32_t* __restrict__ dL) {
    size_t base = ((size_t)blockIdx.y * gridDim.x + blockIdx.x) * (128 * DIM);
    const float2* s = (const float2*)(src + base);
    uint32_t* h = dH + base / 2;
    uint32_t* l = dL + base / 2;
    #pragma unroll
    for (int it = 0; it < 16; it++) {
        int i = threadIdx.x + it * 256;      // 0..4095 float2
        float2 v = s[i];
        uint32_t hh, ll;
        split_pair(v.x, v.y, hh, ll);
        h[i] = hh; l[i] = ll;
    }
}

// ---------------- V pre-split + transpose: [bh][j][d] -> [bh][d][j] --------
__global__ void __launch_bounds__(256) k_vsplit(const float* __restrict__ V) {
    __shared__ float tr[64][33];
    const int jc = blockIdx.x;           // 32-j chunk
    const int bh = blockIdx.y;
    const int tid = threadIdx.x;
    const float* Vb = V + ((size_t)bh * LEN + jc * 32) * DIM;
    #pragma unroll
    for (int rep = 0; rep < 2; rep++) {
        int f4 = tid + rep * 256;
        int jr = f4 >> 4;
        int d4 = (f4 & 15) * 4;
        float4 v = *(const float4*)(Vb + (size_t)jr * DIM + d4);
        tr[d4+0][jr] = v.x; tr[d4+1][jr] = v.y;
        tr[d4+2][jr] = v.z; tr[d4+3][jr] = v.w;
    }
    __syncthreads();
    #pragma unroll
    for (int rep = 0; rep < 4; rep++) {
        int oi = tid + rep * 256;
        int d = oi >> 4, j2 = oi & 15;
        uint32_t h, l;
        split_pair(tr[d][j2*2], tr[d][j2*2+1], h, l);
        size_t gi = ((size_t)bh * DIM + d) * (LEN/2) + jc * 16 + j2;
        g_VH[gi] = h; g_VL[gi] = l;
    }
}

// ---------------------------------------------------------------------------
// 128x128 NT tile body from PRE-SPLIT operands (pure copy fill + 3-product)
// ---------------------------------------------------------------------------
__device__ __forceinline__ void qk_body_pre(const uint32_t* __restrict__ AHg,
                                            const uint32_t* __restrict__ ALg,
                                            const uint32_t* __restrict__ BHg,
                                            const uint32_t* __restrict__ BLg,
                                            uint16_t* sm, float acc[2][8][4]) {
    const int tid = threadIdx.x;
    uint32_t* AH = (uint32_t*)(sm + QK_AH);
    uint32_t* AL = (uint32_t*)(sm + QK_AL);
    uint32_t* BH = (uint32_t*)(sm + QK_BH);
    uint32_t* BL = (uint32_t*)(sm + QK_BL);
    #pragma unroll
    for (int it = 0; it < 4; it++) {
        int idx = tid + it * 256;            // 0..1023: 128 rows x 8 uint4
        int row = idx >> 3;
        int grp = idx & 7;                   // uint4 (4 u32 = 8 bf16) per row
        const uint4* a_h = (const uint4*)(AHg + (size_t)row * 32) + grp;
        const uint4* a_l = (const uint4*)(ALg + (size_t)row * 32) + grp;
        const uint4* b_h = (const uint4*)(BHg + (size_t)row * 32) + grp;
        const uint4* b_l = (const uint4*)(BLg + (size_t)row * 32) + grp;
        int so = row * 9 + grp;              // uint4 smem index (stride 144B)
        ((uint4*)AH)[so] = *a_h;
        ((uint4*)AL)[so] = *a_l;
        ((uint4*)BH)[so] = *b_h;
        ((uint4*)BL)[so] = *b_l;
    }
    __syncthreads();

    const int w = tid >> 5, lane = tid & 31;
    const int wr = w >> 1, wc = w & 1;
    const int g = lane >> 2, t = lane & 3;
    #pragma unroll
    for (int ks = 0; ks < 4; ks++) {
        const int k0 = ks * 16 + 2 * t;
        uint32_t ah[2][4], al[2][4];
        #pragma unroll
        for (int mi = 0; mi < 2; mi++) {
            int r = wr * 32 + mi * 16 + g;
            int o0 = (r * STQ + k0) >> 1, o1 = ((r + 8) * STQ + k0) >> 1;
            ah[mi][0] = AH[o0];     ah[mi][1] = AH[o1];
            ah[mi][2] = AH[o0 + 4]; ah[mi][3] = AH[o1 + 4];
            al[mi][0] = AL[o0];     al[mi][1] = AL[o1];
            al[mi][2] = AL[o0 + 4]; al[mi][3] = AL[o1 + 4];
        }
        #pragma unroll
        for (int ni = 0; ni < 8; ni++) {
            int n = wc * 64 + ni * 8 + g;
            int ob = (n * STQ + k0) >> 1;
            uint32_t bh0 = BH[ob], bh1 = BH[ob + 4];
            uint32_t bl0 = BL[ob], bl1 = BL[ob + 4];
            #pragma unroll
            for (int mi = 0; mi < 2; mi++) {
                mma16816(acc[mi][ni], ah[mi][0], ah[mi][1], ah[mi][2], ah[mi][3], bh0, bh1);
                mma16816(acc[mi][ni], ah[mi][0], ah[mi][1], ah[mi][2], ah[mi][3], bl0, bl1);
                mma16816(acc[mi][ni], al[mi][0], al[mi][1], al[mi][2], al[mi][3], bh0, bh1);
            }
        }
    }
}

// ---------------- R = Q @ embed^T (pruned tiles) ---------------------------
__global__ void __launch_bounds__(256, 2) k_relgemm(int dummy) {
    const int rt = blockIdx.x, ct = blockIdx.y, bh = blockIdx.z;
    if (rt + ct <= 6) return;            // R[q,e] read only where e >= 1023-q
    extern __shared__ uint16_t smq[];
    float acc[2][8][4];
    #pragma unroll
    for (int a = 0; a < 2; a++)
        #pragma unroll
        for (int b = 0; b < 8; b++)
            #pragma unroll
            for (int c = 0; c < 4; c++) acc[a][b][c] = 0.f;
    const size_t qb = ((size_t)bh * LEN + rt * 128) * 32;
    const size_t eb = (size_t)(ct * 128) * 32;
    qk_body_pre(g_QH + qb, g_QL + qb, g_EH + eb, g_EL + eb, smq, acc);

    const int tid = threadIdx.x, w = tid >> 5, lane = tid & 31;
    const int wr = w >> 1, wc = w & 1, g = lane >> 2, t = lane & 3;
    #pragma unroll
    for (int mi = 0; mi < 2; mi++) {
        int q0 = rt * 128 + wr * 32 + mi * 16 + g;
        float* R0 = g_R + ((size_t)bh * LEN + q0) * MRP + ct * 128;
        float* R1 = R0 + 8 * MRP;
        #pragma unroll
        for (int ni = 0; ni < 8; ni++) {
            int c = wc * 64 + ni * 8 + 2 * t;
            *(float2*)(R0 + c) = make_float2(acc[mi][ni][0], acc[mi][ni][1]);
            *(float2*)(R1 + c) = make_float2(acc[mi][ni][2], acc[mi][ni][3]);
        }
    }
}

// ---------------- S = Q @ K^T + rel (lower-tri tiles) ----------------------
__global__ void __launch_bounds__(256, 2) k_qk(float* __restrict__ Wt) {
    extern __shared__ uint16_t smq[];
    int ti, tj; tri_map(blockIdx.x, ti, tj);
    const int bh = blockIdx.y;
    float acc[2][8][4];
    #pragma unroll
    for (int a = 0; a < 2; a++)
        #pragma unroll
        for (int b = 0; b < 8; b++)
            #pragma unroll
            for (int c = 0; c < 4; c++) acc[a][b][c] = 0.f;
    const size_t qb = ((size_t)bh * LEN + ti * 128) * 32;
    const size_t kb = ((size_t)bh * LEN + tj * 128) * 32;
    qk_body_pre(g_QH + qb, g_QL + qb, g_KH + kb, g_KL + kb, smq, acc);

    const int tid = threadIdx.x, w = tid >> 5, lane = tid & 31;
    const int wr = w >> 1, wc = w & 1, g = lane >> 2, t = lane & 3;
    #pragma unroll
    for (int mi = 0; mi < 2; mi++) {
        #pragma unroll
        for (int rh = 0; rh < 2; rh++) {
            int q0 = ti * 128 + wr * 32 + mi * 16 + g + rh * 8;
            const float* Rrow = g_R + ((size_t)bh * LEN + q0) * MRP;
            float* Wrow = Wt + ((size_t)bh * LEN + q0) * LEN + tj * 128;
            #pragma unroll
            for (int ni = 0; ni < 8; ni++) {
                int c = wc * 64 + ni * 8 + 2 * t;
                int j = tj * 128 + c;
                int rp = j - q0 + (MRP - 1);
                float r0 = (rp >= 0 && rp < MRP) ? Rrow[rp] : 0.f;
                int rp1 = rp + 1;
                float r1 = (rp1 >= 0 && rp1 < MRP) ? Rrow[rp1] : 0.f;
                float x0 = acc[mi][ni][2 * rh + 0] + r0;
                float x1 = acc[mi][ni][2 * rh + 1] + r1;
                *(float2*)(Wrow + c) = make_float2(x0, x1);
            }
        }
    }
}

// ---------------- row softmax ----------------------------------------------
__global__ void __launch_bounds__(256) k_softmax(float* __restrict__ Wt) {
    const int q  = blockIdx.x & (LEN - 1);
    const int bh = blockIdx.x >> 11;
    float* Wrow = Wt + ((size_t)bh * LEN + q) * LEN;
    const int tid = threadIdx.x;
    const int ja = tid * 4, jb = 1024 + tid * 4;
    float4 wa = make_float4(-3e38f, -3e38f, -3e38f, -3e38f), wb = wa;
    if (ja <= q) wa = *(const float4*)(Wrow + ja);
    if (jb <= q) wb = *(const float4*)(Wrow + jb);
    float va[4] = {wa.x, wa.y, wa.z, wa.w};
    float vb[4] = {wb.x, wb.y, wb.z, wb.w};

    float m = -3.0e38f;
    #pragma unroll
    for (int c = 0; c < 4; c++) {
        if (ja + c <= q) m = fmaxf(m, va[c]);
        if (jb + c <= q) m = fmaxf(m, vb[c]);
    }
    __shared__ float red[9];
    #pragma unroll
    for (int o = 16; o > 0; o >>= 1) m = fmaxf(m, __shfl_xor_sync(0xffffffffu, m, o));
    if ((tid & 31) == 0) red[tid >> 5] = m;
    __syncthreads();
    if (tid == 0) {
        float x = red[0];
        #pragma unroll
        for (int w = 1; w < 8; w++) x = fmaxf(x, red[w]);
        red[8] = x;
    }
    __syncthreads();
    const float bm = red[8];

    float ea[4], eb[4], s = 0.f;
    #pragma unroll
    for (int c = 0; c < 4; c++) {
        ea[c] = (ja + c <= q) ? __expf(va[c] - bm) : 0.f;
        eb[c] = (jb + c <= q) ? __expf(vb[c] - bm) : 0.f;
        s += ea[c] + eb[c];
    }
    __syncthreads();
    #pragma unroll
    for (int o = 16; o > 0; o >>= 1) s += __shfl_xor_sync(0xffffffffu, s, o);
    if ((tid & 31) == 0) red[tid >> 5] = s;
    __syncthreads();
    if (tid == 0) {
        float x = red[0];
        #pragma unroll
        for (int w = 1; w < 8; w++) x += red[w];
        red[8] = x;
    }
    __syncthreads();
    const float inv = 1.0f / red[8];
    *(float4*)(Wrow + ja) = make_float4(ea[0]*inv, ea[1]*inv, ea[2]*inv, ea[3]*inv);
    *(float4*)(Wrow + jb) = make_float4(eb[0]*inv, eb[1]*inv, eb[2]*inv, eb[3]*inv);
}

// ---------------- O = W @ V (split-K, register acc, atomic epilogue) -------
__global__ void __launch_bounds__(256, 2) k_pv(const float* __restrict__ Wt,
                                               float* __restrict__ O) {
    extern __shared__ uint16_t smp[];
    const int s = blockIdx.x, bh = blockIdx.y;
    int ti, tj0, tj1;
    if (s < 8) { ti = s; tj0 = 0; tj1 = ti + 1; }
    else {
        int k2 = s - 8; ti = 8 + (k2 >> 1);
        int cnt = ti + 1, first = (cnt + 1) >> 1;
        if (k2 & 1) { tj0 = first; tj1 = cnt; } else { tj0 = 0; tj1 = first; }
    }
    uint32_t* WH = (uint32_t*)(smp + PV_WH);
    uint32_t* WL = (uint32_t*)(smp + PV_WL);
    uint32_t* VH = (uint32_t*)(smp + PV_VH);
    uint32_t* VL = (uint32_t*)(smp + PV_VL);

    const int tid = threadIdx.x, w = tid >> 5, lane = tid & 31;
    const int wr = w >> 1, wc = w & 1, g = lane >> 2, t = lane & 3;

    float acc[2][4][4];
    #pragma unroll
    for (int a = 0; a < 2; a++)
        #pragma unroll
        for (int b = 0; b < 4; b++)
            #pragma unroll
            for (int c = 0; c < 4; c++) acc[a][b][c] = 0.f;

    for (int tj = tj0; tj < tj1; tj++) {
        const float* Wg = Wt + ((size_t)bh * LEN + ti * 128) * LEN + tj * 128;
        __syncthreads();
        #pragma unroll
        for (int it = 0; it < 16; it++) {       // W: 128x128 -> 4096 float4
            int idx = tid + it * 256;
            int row = idx >> 5;
            int c4  = (idx & 31) * 4;
            int so  = (row * STP + c4) >> 1;
            float4 vv = *(const float4*)(Wg + (size_t)row * LEN + c4);
            uint32_t h, l;
            split_pair(vv.x, vv.y, h, l); WH[so] = h;     WL[so] = l;
            split_pair(vv.z, vv.w, h, l); WH[so + 1] = h; WL[so + 1] = l;
        }
        #pragma unroll
        for (int it = 0; it < 4; it++) {        // V: pre-split copy
            int li = tid + it * 256;
            int d = li >> 4, j4 = (li & 15) * 4;
            size_t gi = ((size_t)bh * DIM + d) * (LEN/2) + tj * 64 + j4;
            *(uint4*)&VH[d * 68 + j4] = *(const uint4*)&g_VH[gi];
            *(uint4*)&VL[d * 68 + j4] = *(const uint4*)&g_VL[gi];
        }
        __syncthreads();

        #pragma unroll
        for (int ks = 0; ks < 8; ks++) {
            const int k0 = ks * 16 + 2 * t;
            uint32_t ah[2][4], al[2][4];
            #pragma unroll
            for (int mi = 0; mi < 2; mi++) {
                int r = wr * 32 + mi * 16 + g;
                int o0 = (r * STP + k0) >> 1, o1 = ((r + 8) * STP + k0) >> 1;
                ah[mi][0] = WH[o0];     ah[mi][1] = WH[o1];
                ah[mi][2] = WH[o0 + 4]; ah[mi][3] = WH[o1 + 4];
                al[mi][0] = WL[o0];     al[mi][1] = WL[o1];
                al[mi][2] = WL[o0 + 4]; al[mi][3] = WL[o1 + 4];
            }
            #pragma unroll
            for (int ni = 0; ni < 4; ni++) {
                int n = wc * 32 + ni * 8 + g;
                int ob = (n * STP + k0) >> 1;
                uint32_t bh0 = VH[ob], bh1 = VH[ob + 4];
                uint32_t bl0 = VL[ob], bl1 = VL[ob + 4];
                #pragma unroll
                for (int mi = 0; mi < 2; mi++) {
                    mma16816(acc[mi][ni], ah[mi][0], ah[mi][1], ah[mi][2], ah[mi][3], bh0, bh1);
                    mma16816(acc[mi][ni], ah[mi][0], ah[mi][1], ah[mi][2], ah[mi][3], bl0, bl1);
                    mma16816(acc[mi][ni], al[mi][0], al[mi][1], al[mi][2], al[mi][3], bh0, bh1);
                }
            }
        }
    }

    #pragma unroll
    for (int mi = 0; mi < 2; mi++) {
        #pragma unroll
        for (int rh = 0; rh < 2; rh++) {
            int row = ti * 128 + wr * 32 + mi * 16 + g + rh * 8;
            float* orow = O + ((size_t)bh * LEN + row) * DIM;
            #pragma unroll
            for (int ni = 0; ni < 4; ni++) {
                int c = wc * 32 + ni * 8 + 2 * t;
                atomicAdd(orow + c,     acc[mi][ni][2 * rh + 0]);
                atomicAdd(orow + c + 1, acc[mi][ni][2 * rh + 1]);
            }
        }
    }
}

// ---------------------------------------------------------------------------
extern "C" void kernel_launch(void* const* d_in, const int* in_sizes, int n_in,
                              void* d_out, int out_size) {
    const float* q   = (const float*)d_in[0];
    const float* k   = (const float*)d_in[1];
    const float* v   = (const float*)d_in[2];
    const float* rel = (const float*)d_in[3];

    float* out = (float*)d_out;
    float* Wt  = out + OUT_ELEMS;

    cudaFuncSetAttribute(k_relgemm, cudaFuncAttributeMaxDynamicSharedMemorySize, QK_SMEM);
    cudaFuncSetAttribute(k_qk,      cudaFuncAttributeMaxDynamicSharedMemorySize, QK_SMEM);
    cudaFuncSetAttribute(k_pv,      cudaFuncAttributeMaxDynamicSharedMemorySize, PV_SMEM);

    k_zero<<<(unsigned)(OUT_ELEMS / 1024), 256>>>(out);

    // pre-split all GEMM operands to bf16 hi/lo (one-time)
    uint32_t *qh, *ql, *kh, *kl, *eh, *el;
    cudaGetSymbolAddress((void**)&qh, g_QH);
    cudaGetSymbolAddress((void**)&ql, g_QL);
    cudaGetSymbolAddress((void**)&kh, g_KH);
    cudaGetSymbolAddress((void**)&kl, g_KL);
    cudaGetSymbolAddress((void**)&eh, g_EH);
    cudaGetSymbolAddress((void**)&el, g_EL);
    dim3 gs(QT, BHN);
    k_presplit<<<gs, 256>>>(q, qh, ql);
    k_presplit<<<gs, 256>>>(k, kh, kl);
    dim3 ge(MRP / 128, 1);
    k_presplit<<<ge, 256>>>(rel, eh, el);

    dim3 gv(LEN / 32, BHN);
    k_vsplit<<<gv, 256>>>(v);

    dim3 g0(QT, MRP / 128, BHN);
    k_relgemm<<<g0, 256, QK_SMEM>>>(0);

    dim3 g1(TRI, BHN);
    k_qk<<<g1, 256, QK_SMEM>>>(Wt);

    k_softmax<<<BHN * LEN, 256>>>(Wt);

    dim3 g2(24, BHN);
    k_pv<<<g2, 256, PV_SMEM>>>(Wt, out);
}